// round 6
// baseline (speedup 1.0000x reference)
#include <cuda_runtime.h>
#include <float.h>

#define B_ 2
#define T_ 5
#define C_ 3
#define H_ 96
#define W_ 96
#define WS_ 9
#define WT_ 1
#define PS_ 5
#define PSD_ 7
#define K_ 10
#define S0_ 4
#define NH_ (H_ / S0_)
#define NW_ (W_ / S0_)
#define Q_ (T_ * NH_ * NW_)             // 2880
#define L_ ((2 * WT_ + 1) * WS_ * WS_)  // 243
#define LSELF_ (WT_ * WS_ * WS_ + (WS_ / 2) * WS_ + (WS_ / 2))  // 121
#define GRID_ (B_ * Q_)                 // 5760
#define HW_ (H_ * W_)                   // 9216

#define TR_ 15
#define TSTR_ 17
#define TPLANE_ (TR_ * TSTR_)           // 255

typedef unsigned long long u64;
#define NEG1X2_ 0xBF800000BF800000ull   // packed {-1.0f, -1.0f}

__device__ __forceinline__ u64 fma2(u64 a, u64 b, u64 c) {
    u64 d;
    asm("fma.rn.f32x2 %0, %1, %2, %3;" : "=l"(d) : "l"(a), "l"(b), "l"(c));
    return d;
}
__device__ __forceinline__ int refl(int i, int n) {
    i = i < 0 ? -i : i;
    return i >= n ? 2 * (n - 1) - i : i;
}
__device__ __forceinline__ int clampi(int i, int lo, int hi) {
    return min(max(i, lo), hi);
}

__global__ void zero_out_k(float* out) { out[0] = 0.0f; }

__global__ __launch_bounds__(256) void dnls_main_k(
    const float* __restrict__ noisy,
    const float* __restrict__ deno,
    float* __restrict__ out)
{
    const int blk = blockIdx.x;
    const int b = blk / Q_;
    const int q = blk % Q_;
    const int qt = q / (NH_ * NW_);
    const int qr = q % (NH_ * NW_);
    const int qh = (qr / NW_) * S0_;
    const int qw = (qr % NW_) * S0_;
    const int tid = threadIdx.x;
    const int lane = tid & 31;

    __shared__ float2 tile01[3 * TPLANE_];   // noisy ch0,1: [slot][15][17]
    __shared__ float  tile2 [3 * TPLANE_];   // noisy ch2
    __shared__ float2 dtile01[TPLANE_];      // deno frame qt ch0,1
    __shared__ float  dtile2 [TPLANE_];      // deno ch2
    __shared__ float  dsm[L_];
    __shared__ int    sel[K_];
    __shared__ int    kbarr[K_ - 1];
    __shared__ int    selt[K_ - 1], selh[K_ - 1], selw[K_ - 1];
    __shared__ float  red[8];

    const float* nb = noisy + (size_t)b * T_ * C_ * HW_;
    const float* db = deno  + (size_t)b * T_ * C_ * HW_;

    const int rlo = max(0, qh - 7);
    const int clo = max(0, qw - 7);
    const int Rn = min(H_ - 1, qh + 7) - rlo + 1;
    const int Cn = min(W_ - 1, qw + 7) - clo + 1;

    const bool interior = (qh >= 8 && qh <= 88 && qw >= 8 && qw <= 88);

    if (interior) {
        // ---- Fast staging: 15x15, no bounds checks ----
        if (tid < 240) {
            int rr = tid >> 4, cc = tid & 15;
            if (cc < 15) {
                int gb = (rlo + rr) * W_ + clo + cc;
                int sb = rr * TSTR_ + cc;
                #pragma unroll
                for (int s = 0; s < 3; s++) {
                    int ft = clampi(qt + s - WT_, 0, T_ - 1);
                    const float* base = nb + (size_t)ft * C_ * HW_ + gb;
                    tile01[s * TPLANE_ + sb] = make_float2(__ldg(base), __ldg(base + HW_));
                    tile2 [s * TPLANE_ + sb] = __ldg(base + 2 * HW_);
                }
                const float* dbase = db + (size_t)qt * C_ * HW_ + gb;
                dtile01[sb] = make_float2(__ldg(dbase), __ldg(dbase + HW_));
                dtile2 [sb] = __ldg(dbase + 2 * HW_);
            }
        }
        __syncthreads();

        // ---- Phase 1 fast: packed f32x2, all offsets immediate ----
        if (tid < L_) {
            int dti = tid / (WS_ * WS_);
            int rem = tid % (WS_ * WS_);
            int dhi = rem / WS_;
            int dwi = rem % WS_;
            const float2* cb01 = tile01 + dti * TPLANE_ + (dhi + 1) * TSTR_ + (dwi + 1);
            const float*  cb2  = tile2  + dti * TPLANE_ + (dhi + 1) * TSTR_ + (dwi + 1);
            const float2* qb01 = tile01 + 1 * TPLANE_ + 5 * TSTR_ + 5;
            const float*  qb2  = tile2  + 1 * TPLANE_ + 5 * TSTR_ + 5;
            u64 acc01 = 0ull;
            float acc2 = 0.0f;
            #pragma unroll
            for (int dy = 0; dy < PS_; dy++) {
                #pragma unroll
                for (int dx = 0; dx < PS_; dx++) {
                    int o = dy * TSTR_ + dx;
                    u64 qv = *reinterpret_cast<const u64*>(qb01 + o);
                    u64 cv = *reinterpret_cast<const u64*>(cb01 + o);
                    u64 d = fma2(cv, NEG1X2_, qv);        // q - c (exact)
                    acc01 = fma2(d, d, acc01);
                    float d2 = qb2[o] - cb2[o];
                    acc2 = fmaf(d2, d2, acc2);
                }
            }
            float lo = __uint_as_float((unsigned)(acc01 & 0xffffffffull));
            float hi = __uint_as_float((unsigned)(acc01 >> 32));
            float acc = (lo + hi) + acc2;
            dsm[tid] = (tid == LSELF_) ? -1.0f : acc;
        }
    } else {
        // ---- General staging (bounds-checked) ----
        for (int idx = tid; idx < 3 * TPLANE_; idx += 256) {
            int s   = idx / TPLANE_;
            int rem = idx % TPLANE_;
            int rr = rem / TSTR_, cc = rem % TSTR_;
            if (rr < Rn && cc < Cn) {
                int ft = clampi(qt + s - WT_, 0, T_ - 1);
                const float* base = nb + (size_t)ft * C_ * HW_ + (rlo + rr) * W_ + (clo + cc);
                tile01[idx] = make_float2(__ldg(base), __ldg(base + HW_));
                tile2 [idx] = __ldg(base + 2 * HW_);
            }
        }
        for (int idx = tid; idx < TPLANE_; idx += 256) {
            int rr = idx / TSTR_, cc = idx % TSTR_;
            if (rr < Rn && cc < Cn) {
                const float* dbase = db + (size_t)qt * C_ * HW_ + (rlo + rr) * W_ + (clo + cc);
                dtile01[idx] = make_float2(__ldg(dbase), __ldg(dbase + HW_));
                dtile2 [idx] = __ldg(dbase + 2 * HW_);
            }
        }
        __syncthreads();

        // ---- Phase 1 general (reflect/clamp) ----
        if (tid < L_) {
            int dti = tid / (WS_ * WS_);
            int rem = tid % (WS_ * WS_);
            int dhi = rem / WS_;
            int dwi = rem % WS_;
            int ch = clampi(qh + dhi - WS_ / 2, 0, H_ - 1);
            int cw = clampi(qw + dwi - WS_ / 2, 0, W_ - 1);
            int crow[PS_], ccol[PS_], qrow[PS_], qcol[PS_];
            #pragma unroll
            for (int d = 0; d < PS_; d++) {
                crow[d] = refl(ch + d - PS_ / 2, H_) - rlo;
                ccol[d] = refl(cw + d - PS_ / 2, W_) - clo;
                qrow[d] = refl(qh + d - PS_ / 2, H_) - rlo;
                qcol[d] = refl(qw + d - PS_ / 2, W_) - clo;
            }
            const float* t01 = (const float*)tile01;
            float acc = 0.0f;
            #pragma unroll
            for (int c = 0; c < C_; c++) {
                #pragma unroll
                for (int dy = 0; dy < PS_; dy++) {
                    #pragma unroll
                    for (int dx = 0; dx < PS_; dx++) {
                        int qp = 1 * TPLANE_ + qrow[dy] * TSTR_ + qcol[dx];
                        int cp = dti * TPLANE_ + crow[dy] * TSTR_ + ccol[dx];
                        float qv = (c < 2) ? t01[2 * qp + c] : tile2[qp];
                        float cv = (c < 2) ? t01[2 * cp + c] : tile2[cp];
                        float df = qv - cv;
                        acc = fmaf(df, df, acc);
                    }
                }
            }
            dsm[tid] = (tid == LSELF_) ? -1.0f : acc;
        }
    }
    __syncthreads();

    // ---- Phase 2: register-resident top-K, lowest-index tie-break (warp 0) ----
    if (tid < 32) {
        u64 keys[8];
        #pragma unroll
        for (int j = 0; j < 8; j++) {
            int i = lane + 32 * j;
            if (i < L_) {
                float v = dsm[i];
                unsigned u = (v < 0.0f) ? 0u : ((unsigned)__float_as_int(v) + 1u);
                keys[j] = ((u64)u << 32) | (unsigned)i;
            } else {
                keys[j] = ~0ull;
            }
        }
        for (int k = 0; k < K_; k++) {
            u64 m = keys[0];
            #pragma unroll
            for (int j = 1; j < 8; j++) m = keys[j] < m ? keys[j] : m;
            #pragma unroll
            for (int off = 16; off; off >>= 1) {
                u64 o = __shfl_down_sync(0xffffffffu, m, off);
                m = o < m ? o : m;
            }
            m = __shfl_sync(0xffffffffu, m, 0);
            int winIdx = (int)(unsigned)(m & 0xffffffffull);
            if (lane == 0) sel[k] = winIdx;
            int wj = winIdx >> 5, wl = winIdx & 31;
            #pragma unroll
            for (int j = 0; j < 8; j++)
                if (j == wj && lane == wl) keys[j] = ~0ull;
        }
    }
    __syncthreads();

    float part = 0.0f;
    if (interior) {
        if (tid < K_ - 1) {
            int l = sel[tid + 1];
            int dti = l / (WS_ * WS_);
            int rem = l % (WS_ * WS_);
            kbarr[tid] = dti * TPLANE_ + (rem / WS_) * TSTR_ + (rem % WS_);  // pixel units
        }
        __syncthreads();

        // ---- Phase 3 fast: thread = (c,dy0,dx0), pd loaded once ----
        if (tid < C_ * PSD_ * PSD_) {       // 147 threads
            int c   = tid / (PSD_ * PSD_);
            int rr  = tid % (PSD_ * PSD_);
            int dy0 = rr / PSD_;
            int dx0 = rr % PSD_;
            int mypix = dy0 * TSTR_ + dx0;
            int pdpix = (dy0 + 4) * TSTR_ + (dx0 + 4);
            const float* t01 = (const float*)tile01;
            const float* d01 = (const float*)dtile01;
            float pd = (c < 2) ? d01[2 * pdpix + c] : dtile2[pdpix];
            int kb[K_ - 1];
            #pragma unroll
            for (int k = 0; k < K_ - 1; k++) kb[k] = kbarr[k] + mypix;
            #pragma unroll
            for (int k = 0; k < K_ - 1; k++) {
                int p = kb[k];
                float pk = (c < 2) ? t01[2 * p + c] : tile2[p];
                float df = pd - pk;
                part = fmaf(df, df, part);
            }
        }
    } else {
        if (tid < K_ - 1) {
            int l = sel[tid + 1];
            int dti = l / (WS_ * WS_);
            int rem = l % (WS_ * WS_);
            selt[tid] = dti;
            selh[tid] = clampi(qh + rem / WS_ - WS_ / 2, 0, H_ - 1);
            selw[tid] = clampi(qw + rem % WS_ - WS_ / 2, 0, W_ - 1);
        }
        __syncthreads();

        const float* t01 = (const float*)tile01;
        const float* d01 = (const float*)dtile01;
        for (int i = tid; i < (K_ - 1) * C_ * PSD_ * PSD_; i += 256) {
            int k = i / (C_ * PSD_ * PSD_);
            int j = i % (C_ * PSD_ * PSD_);
            int c  = j / (PSD_ * PSD_);
            int rr = j % (PSD_ * PSD_);
            int dy = rr / PSD_ - PSD_ / 2;
            int dx = rr % PSD_ - PSD_ / 2;
            int pdp = (refl(qh + dy, H_) - rlo) * TSTR_ + (refl(qw + dx, W_) - clo);
            int pkp = selt[k] * TPLANE_ +
                      (refl(selh[k] + dy, H_) - rlo) * TSTR_ +
                      (refl(selw[k] + dx, W_) - clo);
            float pd = (c < 2) ? d01[2 * pdp + c] : dtile2[pdp];
            float pk = (c < 2) ? t01[2 * pkp + c] : tile2[pkp];
            float df = pd - pk;
            part = fmaf(df, df, part);
        }
    }

    // ---- Block reduction -> atomic accumulate ----
    #pragma unroll
    for (int off = 16; off; off >>= 1)
        part += __shfl_down_sync(0xffffffffu, part, off);
    if ((tid & 31) == 0) red[tid >> 5] = part;
    __syncthreads();
    if (tid == 0) {
        float s = 0.0f;
        #pragma unroll
        for (int w = 0; w < 8; w++) s += red[w];
        atomicAdd(out, s * (1.0f / (float)(GRID_ * (K_ - 1))));
    }
}

extern "C" void kernel_launch(void* const* d_in, const int* in_sizes, int n_in,
                              void* d_out, int out_size) {
    const float* noisy = (const float*)d_in[0];
    const float* deno  = (const float*)d_in[1];
    // d_in[2] = curr_epoch (unused by the reference computation)
    zero_out_k<<<1, 1>>>((float*)d_out);
    dnls_main_k<<<GRID_, 256>>>(noisy, deno, (float*)d_out);
}

// round 7
// speedup vs baseline: 1.0560x; 1.0560x over previous
#include <cuda_runtime.h>
#include <float.h>

#define B_ 2
#define T_ 5
#define C_ 3
#define H_ 96
#define W_ 96
#define WS_ 9
#define WT_ 1
#define PS_ 5
#define PSD_ 7
#define K_ 10
#define S0_ 4
#define NH_ (H_ / S0_)
#define NW_ (W_ / S0_)
#define Q_ (T_ * NH_ * NW_)             // 2880
#define L_ ((2 * WT_ + 1) * WS_ * WS_)  // 243
#define LSELF_ (WT_ * WS_ * WS_ + (WS_ / 2) * WS_ + (WS_ / 2))  // 121
#define GRID_ (B_ * Q_)                 // 5760
#define HW_ (H_ * W_)                   // 9216

#define TR_ 15
#define TSTR_ 17
#define TPLANE_ (TR_ * TSTR_)           // 255

typedef unsigned long long u64;
#define NEG1X2_ 0xBF800000BF800000ull   // packed {-1.0f, -1.0f}

__device__ __forceinline__ u64 fma2(u64 a, u64 b, u64 c) {
    u64 d;
    asm("fma.rn.f32x2 %0, %1, %2, %3;" : "=l"(d) : "l"(a), "l"(b), "l"(c));
    return d;
}
__device__ __forceinline__ int refl(int i, int n) {
    i = i < 0 ? -i : i;
    return i >= n ? 2 * (n - 1) - i : i;
}
__device__ __forceinline__ int clampi(int i, int lo, int hi) {
    return min(max(i, lo), hi);
}

__global__ void zero_out_k(float* out) { out[0] = 0.0f; }

__global__ __launch_bounds__(256, 5) void dnls_main_k(
    const float* __restrict__ noisy,
    const float* __restrict__ deno,
    float* __restrict__ out)
{
    const int blk = blockIdx.x;
    const int b = blk / Q_;
    const int q = blk % Q_;
    const int qt = q / (NH_ * NW_);
    const int qr = q % (NH_ * NW_);
    const int qh = (qr / NW_) * S0_;
    const int qw = (qr % NW_) * S0_;
    const int tid = threadIdx.x;

    __shared__ float2 tile01[3 * TPLANE_];   // noisy ch0,1: [slot][15][17]
    __shared__ float  tile2 [3 * TPLANE_];   // noisy ch2
    __shared__ float2 dtile01[TPLANE_];      // deno frame qt ch0,1
    __shared__ float  dtile2 [TPLANE_];      // deno ch2
    __shared__ float  dsm[L_];
    __shared__ int    sel[K_];
    __shared__ int    kbarr[K_ - 1];
    __shared__ int    selt[K_ - 1], selh[K_ - 1], selw[K_ - 1];
    __shared__ float  red[8];

    const float* nb = noisy + (size_t)b * T_ * C_ * HW_;
    const float* db = deno  + (size_t)b * T_ * C_ * HW_;

    const int rlo = max(0, qh - 7);
    const int clo = max(0, qw - 7);
    const int Rn = min(H_ - 1, qh + 7) - rlo + 1;
    const int Cn = min(W_ - 1, qw + 7) - clo + 1;

    const bool interior = (qh >= 8 && qh <= 88 && qw >= 8 && qw <= 88);

    if (interior) {
        // ---- Fast staging: 15x15, no bounds checks ----
        if (tid < 240) {
            int rr = tid >> 4, cc = tid & 15;
            if (cc < 15) {
                int gb = (rlo + rr) * W_ + clo + cc;
                int sb = rr * TSTR_ + cc;
                #pragma unroll
                for (int s = 0; s < 3; s++) {
                    int ft = clampi(qt + s - WT_, 0, T_ - 1);
                    const float* base = nb + (size_t)ft * C_ * HW_ + gb;
                    tile01[s * TPLANE_ + sb] = make_float2(__ldg(base), __ldg(base + HW_));
                    tile2 [s * TPLANE_ + sb] = __ldg(base + 2 * HW_);
                }
                const float* dbase = db + (size_t)qt * C_ * HW_ + gb;
                dtile01[sb] = make_float2(__ldg(dbase), __ldg(dbase + HW_));
                dtile2 [sb] = __ldg(dbase + 2 * HW_);
            }
        }
        __syncthreads();

        // ---- Phase 1 fast: packed f32x2, all offsets immediate ----
        if (tid < L_) {
            int dti = tid / (WS_ * WS_);
            int rem = tid % (WS_ * WS_);
            int dhi = rem / WS_;
            int dwi = rem % WS_;
            const float2* cb01 = tile01 + dti * TPLANE_ + (dhi + 1) * TSTR_ + (dwi + 1);
            const float*  cb2  = tile2  + dti * TPLANE_ + (dhi + 1) * TSTR_ + (dwi + 1);
            const float2* qb01 = tile01 + 1 * TPLANE_ + 5 * TSTR_ + 5;
            const float*  qb2  = tile2  + 1 * TPLANE_ + 5 * TSTR_ + 5;
            u64 acc01 = 0ull;
            float acc2 = 0.0f;
            #pragma unroll
            for (int dy = 0; dy < PS_; dy++) {
                #pragma unroll
                for (int dx = 0; dx < PS_; dx++) {
                    int o = dy * TSTR_ + dx;
                    u64 qv = *reinterpret_cast<const u64*>(qb01 + o);
                    u64 cv = *reinterpret_cast<const u64*>(cb01 + o);
                    u64 d = fma2(cv, NEG1X2_, qv);        // q - c (exact)
                    acc01 = fma2(d, d, acc01);
                    float d2 = qb2[o] - cb2[o];
                    acc2 = fmaf(d2, d2, acc2);
                }
            }
            float lo = __uint_as_float((unsigned)(acc01 & 0xffffffffull));
            float hi = __uint_as_float((unsigned)(acc01 >> 32));
            float acc = (lo + hi) + acc2;
            dsm[tid] = (tid == LSELF_) ? -1.0f : acc;
        }
    } else {
        // ---- General staging (bounds-checked) ----
        for (int idx = tid; idx < 3 * TPLANE_; idx += 256) {
            int s   = idx / TPLANE_;
            int rem = idx % TPLANE_;
            int rr = rem / TSTR_, cc = rem % TSTR_;
            if (rr < Rn && cc < Cn) {
                int ft = clampi(qt + s - WT_, 0, T_ - 1);
                const float* base = nb + (size_t)ft * C_ * HW_ + (rlo + rr) * W_ + (clo + cc);
                tile01[idx] = make_float2(__ldg(base), __ldg(base + HW_));
                tile2 [idx] = __ldg(base + 2 * HW_);
            }
        }
        for (int idx = tid; idx < TPLANE_; idx += 256) {
            int rr = idx / TSTR_, cc = idx % TSTR_;
            if (rr < Rn && cc < Cn) {
                const float* dbase = db + (size_t)qt * C_ * HW_ + (rlo + rr) * W_ + (clo + cc);
                dtile01[idx] = make_float2(__ldg(dbase), __ldg(dbase + HW_));
                dtile2 [idx] = __ldg(dbase + 2 * HW_);
            }
        }
        __syncthreads();

        // ---- Phase 1 general (reflect/clamp) ----
        if (tid < L_) {
            int dti = tid / (WS_ * WS_);
            int rem = tid % (WS_ * WS_);
            int dhi = rem / WS_;
            int dwi = rem % WS_;
            int ch = clampi(qh + dhi - WS_ / 2, 0, H_ - 1);
            int cw = clampi(qw + dwi - WS_ / 2, 0, W_ - 1);
            int crow[PS_], ccol[PS_], qrow[PS_], qcol[PS_];
            #pragma unroll
            for (int d = 0; d < PS_; d++) {
                crow[d] = refl(ch + d - PS_ / 2, H_) - rlo;
                ccol[d] = refl(cw + d - PS_ / 2, W_) - clo;
                qrow[d] = refl(qh + d - PS_ / 2, H_) - rlo;
                qcol[d] = refl(qw + d - PS_ / 2, W_) - clo;
            }
            const float* t01 = (const float*)tile01;
            float acc = 0.0f;
            #pragma unroll
            for (int c = 0; c < C_; c++) {
                #pragma unroll
                for (int dy = 0; dy < PS_; dy++) {
                    #pragma unroll
                    for (int dx = 0; dx < PS_; dx++) {
                        int qp = 1 * TPLANE_ + qrow[dy] * TSTR_ + qcol[dx];
                        int cp = dti * TPLANE_ + crow[dy] * TSTR_ + ccol[dx];
                        float qv = (c < 2) ? t01[2 * qp + c] : tile2[qp];
                        float cv = (c < 2) ? t01[2 * cp + c] : tile2[cp];
                        float df = qv - cv;
                        acc = fmaf(df, df, acc);
                    }
                }
            }
            dsm[tid] = (tid == LSELF_) ? -1.0f : acc;
        }
    }
    __syncthreads();

    // ---- Phase 2: K smallest via smem rescan, lowest-index tie-break (warp 0) ----
    if (tid < 32) {
        for (int k = 0; k < K_; k++) {
            float bd = FLT_MAX;
            int   bi = 1 << 20;
            for (int i = tid; i < L_; i += 32) {
                float v = dsm[i];
                if (v < bd) { bd = v; bi = i; }
            }
            #pragma unroll
            for (int off = 16; off; off >>= 1) {
                float od = __shfl_down_sync(0xffffffffu, bd, off);
                int   oi = __shfl_down_sync(0xffffffffu, bi, off);
                if (od < bd || (od == bd && oi < bi)) { bd = od; bi = oi; }
            }
            bi = __shfl_sync(0xffffffffu, bi, 0);
            if (tid == 0) { sel[k] = bi; dsm[bi] = FLT_MAX; }
            __syncwarp();
        }
    }
    __syncthreads();

    float part = 0.0f;
    if (interior) {
        if (tid < K_ - 1) {
            int l = sel[tid + 1];
            int dti = l / (WS_ * WS_);
            int rem = l % (WS_ * WS_);
            kbarr[tid] = dti * TPLANE_ + (rem / WS_) * TSTR_ + (rem % WS_);  // pixel units
        }
        __syncthreads();

        // ---- Phase 3 fast: thread = (c,dy0,dx0), pd loaded once ----
        if (tid < C_ * PSD_ * PSD_) {       // 147 threads
            int c   = tid / (PSD_ * PSD_);
            int rr  = tid % (PSD_ * PSD_);
            int dy0 = rr / PSD_;
            int dx0 = rr % PSD_;
            int mypix = dy0 * TSTR_ + dx0;
            int pdpix = (dy0 + 4) * TSTR_ + (dx0 + 4);
            const float* t01 = (const float*)tile01;
            const float* d01 = (const float*)dtile01;
            float pd = (c < 2) ? d01[2 * pdpix + c] : dtile2[pdpix];
            #pragma unroll
            for (int k = 0; k < K_ - 1; k++) {
                int p = kbarr[k] + mypix;
                float pk = (c < 2) ? t01[2 * p + c] : tile2[p];
                float df = pd - pk;
                part = fmaf(df, df, part);
            }
        }
    } else {
        if (tid < K_ - 1) {
            int l = sel[tid + 1];
            int dti = l / (WS_ * WS_);
            int rem = l % (WS_ * WS_);
            selt[tid] = dti;
            selh[tid] = clampi(qh + rem / WS_ - WS_ / 2, 0, H_ - 1);
            selw[tid] = clampi(qw + rem % WS_ - WS_ / 2, 0, W_ - 1);
        }
        __syncthreads();

        const float* t01 = (const float*)tile01;
        const float* d01 = (const float*)dtile01;
        for (int i = tid; i < (K_ - 1) * C_ * PSD_ * PSD_; i += 256) {
            int k = i / (C_ * PSD_ * PSD_);
            int j = i % (C_ * PSD_ * PSD_);
            int c  = j / (PSD_ * PSD_);
            int rr = j % (PSD_ * PSD_);
            int dy = rr / PSD_ - PSD_ / 2;
            int dx = rr % PSD_ - PSD_ / 2;
            int pdp = (refl(qh + dy, H_) - rlo) * TSTR_ + (refl(qw + dx, W_) - clo);
            int pkp = selt[k] * TPLANE_ +
                      (refl(selh[k] + dy, H_) - rlo) * TSTR_ +
                      (refl(selw[k] + dx, W_) - clo);
            float pd = (c < 2) ? d01[2 * pdp + c] : dtile2[pdp];
            float pk = (c < 2) ? t01[2 * pkp + c] : tile2[pkp];
            float df = pd - pk;
            part = fmaf(df, df, part);
        }
    }

    // ---- Block reduction -> atomic accumulate ----
    #pragma unroll
    for (int off = 16; off; off >>= 1)
        part += __shfl_down_sync(0xffffffffu, part, off);
    if ((tid & 31) == 0) red[tid >> 5] = part;
    __syncthreads();
    if (tid == 0) {
        float s = 0.0f;
        #pragma unroll
        for (int w = 0; w < 8; w++) s += red[w];
        atomicAdd(out, s * (1.0f / (float)(GRID_ * (K_ - 1))));
    }
}

extern "C" void kernel_launch(void* const* d_in, const int* in_sizes, int n_in,
                              void* d_out, int out_size) {
    const float* noisy = (const float*)d_in[0];
    const float* deno  = (const float*)d_in[1];
    // d_in[2] = curr_epoch (unused by the reference computation)
    zero_out_k<<<1, 1>>>((float*)d_out);
    dnls_main_k<<<GRID_, 256>>>(noisy, deno, (float*)d_out);
}

// round 8
// speedup vs baseline: 1.2141x; 1.1497x over previous
#include <cuda_runtime.h>
#include <float.h>

#define B_ 2
#define T_ 5
#define C_ 3
#define H_ 96
#define W_ 96
#define WS_ 9
#define WT_ 1
#define PS_ 5
#define PSD_ 7
#define K_ 10
#define S0_ 4
#define NH_ (H_ / S0_)
#define NW_ (W_ / S0_)
#define Q_ (T_ * NH_ * NW_)             // 2880
#define L_ ((2 * WT_ + 1) * WS_ * WS_)  // 243
#define LSELF_ (WT_ * WS_ * WS_ + (WS_ / 2) * WS_ + (WS_ / 2))  // 121
#define GRID_ (B_ * Q_)                 // 5760
#define HW_ (H_ * W_)                   // 9216

#define TR_ 15
#define TSTR_ 17
#define TPLANE_ (TR_ * TSTR_)           // 255

typedef unsigned long long u64;
#define NEG1X2_ 0xBF800000BF800000ull   // packed {-1.0f, -1.0f}

__device__ __forceinline__ u64 fma2(u64 a, u64 b, u64 c) {
    u64 d;
    asm("fma.rn.f32x2 %0, %1, %2, %3;" : "=l"(d) : "l"(a), "l"(b), "l"(c));
    return d;
}
__device__ __forceinline__ float f32x2_sum(u64 v) {
    return __uint_as_float((unsigned)(v & 0xffffffffull))
         + __uint_as_float((unsigned)(v >> 32));
}
__device__ __forceinline__ int refl(int i, int n) {
    i = i < 0 ? -i : i;
    return i >= n ? 2 * (n - 1) - i : i;
}
__device__ __forceinline__ int clampi(int i, int lo, int hi) {
    return min(max(i, lo), hi);
}

__global__ void zero_out_k(float* out) { out[0] = 0.0f; }

__global__ __launch_bounds__(256, 6) void dnls_main_k(
    const float* __restrict__ noisy,
    const float* __restrict__ deno,
    float* __restrict__ out)
{
    const int blk = blockIdx.x;
    const int b = blk / Q_;
    const int q = blk % Q_;
    const int qt = q / (NH_ * NW_);
    const int qr = q % (NH_ * NW_);
    const int qh = (qr / NW_) * S0_;
    const int qw = (qr % NW_) * S0_;
    const int tid = threadIdx.x;

    __shared__ float4 tile4 [3 * TPLANE_];   // noisy {c0,c1,c2,0}: [slot][15][17]
    __shared__ float4 dtile4[TPLANE_];       // deno frame qt {c0,c1,c2,0}
    __shared__ float  dsm[L_];
    __shared__ int    sel[K_];
    __shared__ int    kbarr[K_ - 1];
    __shared__ int    selt[K_ - 1], selh[K_ - 1], selw[K_ - 1];
    __shared__ float  red[8];

    const float* nb = noisy + (size_t)b * T_ * C_ * HW_;
    const float* db = deno  + (size_t)b * T_ * C_ * HW_;

    const int rlo = max(0, qh - 7);
    const int clo = max(0, qw - 7);
    const int Rn = min(H_ - 1, qh + 7) - rlo + 1;
    const int Cn = min(W_ - 1, qw + 7) - clo + 1;

    const bool interior = (qh >= 8 && qh <= 88 && qw >= 8 && qw <= 88);

    if (interior) {
        // ---- Fast staging: 15x15, no bounds checks ----
        if (tid < 240) {
            int rr = tid >> 4, cc = tid & 15;
            if (cc < 15) {
                int gb = (rlo + rr) * W_ + clo + cc;
                int sb = rr * TSTR_ + cc;
                #pragma unroll
                for (int s = 0; s < 3; s++) {
                    int ft = clampi(qt + s - WT_, 0, T_ - 1);
                    const float* base = nb + (size_t)ft * C_ * HW_ + gb;
                    tile4[s * TPLANE_ + sb] =
                        make_float4(__ldg(base), __ldg(base + HW_), __ldg(base + 2 * HW_), 0.0f);
                }
                const float* dbase = db + (size_t)qt * C_ * HW_ + gb;
                dtile4[sb] =
                    make_float4(__ldg(dbase), __ldg(dbase + HW_), __ldg(dbase + 2 * HW_), 0.0f);
            }
        }
        __syncthreads();

        // ---- Phase 1 fast: one LDS.128 per side per tap, packed f32x2 math ----
        if (tid < L_) {
            int dti = tid / (WS_ * WS_);
            int rem = tid % (WS_ * WS_);
            int dhi = rem / WS_;
            int dwi = rem % WS_;
            const ulonglong2* cb =
                reinterpret_cast<const ulonglong2*>(tile4 + dti * TPLANE_ + (dhi + 1) * TSTR_ + (dwi + 1));
            const ulonglong2* qb =
                reinterpret_cast<const ulonglong2*>(tile4 + 1 * TPLANE_ + 5 * TSTR_ + 5);
            u64 acc01 = 0ull, acc2p = 0ull;
            #pragma unroll
            for (int dy = 0; dy < PS_; dy++) {
                #pragma unroll
                for (int dx = 0; dx < PS_; dx++) {
                    int o = dy * TSTR_ + dx;
                    ulonglong2 qv = qb[o];
                    ulonglong2 cv = cb[o];
                    u64 d01 = fma2(cv.x, NEG1X2_, qv.x);   // {q0-c0, q1-c1}
                    acc01 = fma2(d01, d01, acc01);
                    u64 d2p = fma2(cv.y, NEG1X2_, qv.y);   // {q2-c2, 0}
                    acc2p = fma2(d2p, d2p, acc2p);
                }
            }
            float acc = f32x2_sum(acc01) + f32x2_sum(acc2p);
            dsm[tid] = (tid == LSELF_) ? -1.0f : acc;
        }
    } else {
        // ---- General staging (bounds-checked) ----
        for (int idx = tid; idx < 3 * TPLANE_; idx += 256) {
            int s   = idx / TPLANE_;
            int rem = idx % TPLANE_;
            int rr = rem / TSTR_, cc = rem % TSTR_;
            if (rr < Rn && cc < Cn) {
                int ft = clampi(qt + s - WT_, 0, T_ - 1);
                const float* base = nb + (size_t)ft * C_ * HW_ + (rlo + rr) * W_ + (clo + cc);
                tile4[idx] =
                    make_float4(__ldg(base), __ldg(base + HW_), __ldg(base + 2 * HW_), 0.0f);
            }
        }
        for (int idx = tid; idx < TPLANE_; idx += 256) {
            int rr = idx / TSTR_, cc = idx % TSTR_;
            if (rr < Rn && cc < Cn) {
                const float* dbase = db + (size_t)qt * C_ * HW_ + (rlo + rr) * W_ + (clo + cc);
                dtile4[idx] =
                    make_float4(__ldg(dbase), __ldg(dbase + HW_), __ldg(dbase + 2 * HW_), 0.0f);
            }
        }
        __syncthreads();

        // ---- Phase 1 general (reflect/clamp), LDS.128 per tap ----
        if (tid < L_) {
            int dti = tid / (WS_ * WS_);
            int rem = tid % (WS_ * WS_);
            int dhi = rem / WS_;
            int dwi = rem % WS_;
            int ch = clampi(qh + dhi - WS_ / 2, 0, H_ - 1);
            int cw = clampi(qw + dwi - WS_ / 2, 0, W_ - 1);
            int crow[PS_], ccol[PS_], qrow[PS_], qcol[PS_];
            #pragma unroll
            for (int d = 0; d < PS_; d++) {
                crow[d] = refl(ch + d - PS_ / 2, H_) - rlo;
                ccol[d] = refl(cw + d - PS_ / 2, W_) - clo;
                qrow[d] = refl(qh + d - PS_ / 2, H_) - rlo;
                qcol[d] = refl(qw + d - PS_ / 2, W_) - clo;
            }
            const ulonglong2* t4 = reinterpret_cast<const ulonglong2*>(tile4);
            u64 acc01 = 0ull, acc2p = 0ull;
            #pragma unroll
            for (int dy = 0; dy < PS_; dy++) {
                #pragma unroll
                for (int dx = 0; dx < PS_; dx++) {
                    int qp = 1 * TPLANE_ + qrow[dy] * TSTR_ + qcol[dx];
                    int cp = dti * TPLANE_ + crow[dy] * TSTR_ + ccol[dx];
                    ulonglong2 qv = t4[qp];
                    ulonglong2 cv = t4[cp];
                    u64 d01 = fma2(cv.x, NEG1X2_, qv.x);
                    acc01 = fma2(d01, d01, acc01);
                    u64 d2p = fma2(cv.y, NEG1X2_, qv.y);
                    acc2p = fma2(d2p, d2p, acc2p);
                }
            }
            float acc = f32x2_sum(acc01) + f32x2_sum(acc2p);
            dsm[tid] = (tid == LSELF_) ? -1.0f : acc;
        }
    }
    __syncthreads();

    // ---- Phase 2: K smallest via smem rescan, lowest-index tie-break (warp 0) ----
    if (tid < 32) {
        for (int k = 0; k < K_; k++) {
            float bd = FLT_MAX;
            int   bi = 1 << 20;
            for (int i = tid; i < L_; i += 32) {
                float v = dsm[i];
                if (v < bd) { bd = v; bi = i; }
            }
            #pragma unroll
            for (int off = 16; off; off >>= 1) {
                float od = __shfl_down_sync(0xffffffffu, bd, off);
                int   oi = __shfl_down_sync(0xffffffffu, bi, off);
                if (od < bd || (od == bd && oi < bi)) { bd = od; bi = oi; }
            }
            bi = __shfl_sync(0xffffffffu, bi, 0);
            if (tid == 0) { sel[k] = bi; dsm[bi] = FLT_MAX; }
            __syncwarp();
        }
    }
    __syncthreads();

    float part = 0.0f;
    const float* tf = (const float*)tile4;
    const float* df4 = (const float*)dtile4;
    if (interior) {
        if (tid < K_ - 1) {
            int l = sel[tid + 1];
            int dti = l / (WS_ * WS_);
            int rem = l % (WS_ * WS_);
            kbarr[tid] = dti * TPLANE_ + (rem / WS_) * TSTR_ + (rem % WS_);  // pixel units
        }
        __syncthreads();

        // ---- Phase 3 fast: thread = (c,dy0,dx0), pd loaded once ----
        if (tid < C_ * PSD_ * PSD_) {       // 147 threads
            int c   = tid / (PSD_ * PSD_);
            int rr  = tid % (PSD_ * PSD_);
            int dy0 = rr / PSD_;
            int dx0 = rr % PSD_;
            int mypix = dy0 * TSTR_ + dx0;
            float pd = df4[4 * ((dy0 + 4) * TSTR_ + (dx0 + 4)) + c];
            #pragma unroll
            for (int k = 0; k < K_ - 1; k++) {
                float pk = tf[4 * (kbarr[k] + mypix) + c];
                float dfv = pd - pk;
                part = fmaf(dfv, dfv, part);
            }
        }
    } else {
        if (tid < K_ - 1) {
            int l = sel[tid + 1];
            int dti = l / (WS_ * WS_);
            int rem = l % (WS_ * WS_);
            selt[tid] = dti;
            selh[tid] = clampi(qh + rem / WS_ - WS_ / 2, 0, H_ - 1);
            selw[tid] = clampi(qw + rem % WS_ - WS_ / 2, 0, W_ - 1);
        }
        __syncthreads();

        for (int i = tid; i < (K_ - 1) * C_ * PSD_ * PSD_; i += 256) {
            int k = i / (C_ * PSD_ * PSD_);
            int j = i % (C_ * PSD_ * PSD_);
            int c  = j / (PSD_ * PSD_);
            int rr = j % (PSD_ * PSD_);
            int dy = rr / PSD_ - PSD_ / 2;
            int dx = rr % PSD_ - PSD_ / 2;
            int pdp = (refl(qh + dy, H_) - rlo) * TSTR_ + (refl(qw + dx, W_) - clo);
            int pkp = selt[k] * TPLANE_ +
                      (refl(selh[k] + dy, H_) - rlo) * TSTR_ +
                      (refl(selw[k] + dx, W_) - clo);
            float pd = df4[4 * pdp + c];
            float pk = tf[4 * pkp + c];
            float dfv = pd - pk;
            part = fmaf(dfv, dfv, part);
        }
    }

    // ---- Block reduction -> atomic accumulate ----
    #pragma unroll
    for (int off = 16; off; off >>= 1)
        part += __shfl_down_sync(0xffffffffu, part, off);
    if ((tid & 31) == 0) red[tid >> 5] = part;
    __syncthreads();
    if (tid == 0) {
        float s = 0.0f;
        #pragma unroll
        for (int w = 0; w < 8; w++) s += red[w];
        atomicAdd(out, s * (1.0f / (float)(GRID_ * (K_ - 1))));
    }
}

extern "C" void kernel_launch(void* const* d_in, const int* in_sizes, int n_in,
                              void* d_out, int out_size) {
    const float* noisy = (const float*)d_in[0];
    const float* deno  = (const float*)d_in[1];
    // d_in[2] = curr_epoch (unused by the reference computation)
    zero_out_k<<<1, 1>>>((float*)d_out);
    dnls_main_k<<<GRID_, 256>>>(noisy, deno, (float*)d_out);
}

// round 9
// speedup vs baseline: 1.2464x; 1.0266x over previous
#include <cuda_runtime.h>
#include <float.h>

#define B_ 2
#define T_ 5
#define C_ 3
#define H_ 96
#define W_ 96
#define WS_ 9
#define WT_ 1
#define PS_ 5
#define PSD_ 7
#define K_ 10
#define S0_ 4
#define NH_ (H_ / S0_)
#define NW_ (W_ / S0_)
#define Q_ (T_ * NH_ * NW_)             // 2880
#define L_ ((2 * WT_ + 1) * WS_ * WS_)  // 243
#define LSELF_ (WT_ * WS_ * WS_ + (WS_ / 2) * WS_ + (WS_ / 2))  // 121
#define GRID_ (B_ * Q_)                 // 5760
#define HW_ (H_ * W_)                   // 9216

#define TR_ 15
#define TSTR_ 17
#define TPLANE_ (TR_ * TSTR_)           // 255

typedef unsigned long long u64;
#define NEG1X2_ 0xBF800000BF800000ull   // packed {-1.0f, -1.0f}

__device__ __forceinline__ u64 fma2(u64 a, u64 b, u64 c) {
    u64 d;
    asm("fma.rn.f32x2 %0, %1, %2, %3;" : "=l"(d) : "l"(a), "l"(b), "l"(c));
    return d;
}
__device__ __forceinline__ float f32x2_sum(u64 v) {
    return __uint_as_float((unsigned)(v & 0xffffffffull))
         + __uint_as_float((unsigned)(v >> 32));
}
__device__ __forceinline__ int refl(int i, int n) {
    i = i < 0 ? -i : i;
    return i >= n ? 2 * (n - 1) - i : i;
}
__device__ __forceinline__ int clampi(int i, int lo, int hi) {
    return min(max(i, lo), hi);
}

__global__ void zero_out_k(float* out) { out[0] = 0.0f; }

__global__ __launch_bounds__(256, 6) void dnls_main_k(
    const float* __restrict__ noisy,
    const float* __restrict__ deno,
    float* __restrict__ out)
{
    const int blk = blockIdx.x;
    const int b = blk / Q_;
    const int q = blk % Q_;
    const int qt = q / (NH_ * NW_);
    const int qr = q % (NH_ * NW_);
    const int qh = (qr / NW_) * S0_;
    const int qw = (qr % NW_) * S0_;
    const int tid = threadIdx.x;

    __shared__ float4 tile4 [3 * TPLANE_];   // noisy {c0,c1,c2,0}: [slot][15][17]
    __shared__ float4 dtile4[TPLANE_];       // deno frame qt {c0,c1,c2,0}
    __shared__ float  dsm[L_];
    __shared__ int    sel[K_];
    __shared__ int    kbarr[K_ - 1];
    __shared__ int    selt[K_ - 1], selh[K_ - 1], selw[K_ - 1];
    __shared__ float  red[8];

    const float* nb = noisy + (size_t)b * T_ * C_ * HW_;
    const float* db = deno  + (size_t)b * T_ * C_ * HW_;

    const int rlo = max(0, qh - 7);
    const int clo = max(0, qw - 7);
    const int Rn = min(H_ - 1, qh + 7) - rlo + 1;
    const int Cn = min(W_ - 1, qw + 7) - clo + 1;

    const bool interior = (qh >= 8 && qh <= 88 && qw >= 8 && qw <= 88);

    // per-thread state carried across the phase-1 split (interior path)
    float s0 = 0.0f, s1 = 0.0f, s2 = 0.0f;
    int cand0 = -1;

    if (interior) {
        // ---- Fast staging: 15x15, no bounds checks ----
        if (tid < 240) {
            int rr = tid >> 4, cc = tid & 15;
            if (cc < 15) {
                int gb = (rlo + rr) * W_ + clo + cc;
                int sb = rr * TSTR_ + cc;
                #pragma unroll
                for (int s = 0; s < 3; s++) {
                    int ft = clampi(qt + s - WT_, 0, T_ - 1);
                    const float* base = nb + (size_t)ft * C_ * HW_ + gb;
                    tile4[s * TPLANE_ + sb] =
                        make_float4(__ldg(base), __ldg(base + HW_), __ldg(base + 2 * HW_), 0.0f);
                }
                const float* dbase = db + (size_t)qt * C_ * HW_ + gb;
                dtile4[sb] =
                    make_float4(__ldg(dbase), __ldg(dbase + HW_), __ldg(dbase + 2 * HW_), 0.0f);
            }
        }
        __syncthreads();

        // ---- Phase 1 fast: 1 thread = 3 adjacent-dwi candidates, one u64
        //      channel-half per thread group. 7-wide column window shared. ----
        if (tid < 162) {
            const int grp = (tid < 81) ? 0 : 1;       // 0: {c0,c1}, 1: {c2,pad}
            const int r   = (grp == 0) ? tid : tid - 81;
            const int dti = r / 27;
            const int rr  = r % 27;
            const int dhi = rr / 3;
            const int wg  = rr % 3;                    // dwi in {3wg, 3wg+1, 3wg+2}
            cand0 = dti * 81 + dhi * 9 + 3 * wg;

            const u64* t8 = reinterpret_cast<const u64*>(tile4);
            const int cbase = dti * TPLANE_ + (dhi + 1) * TSTR_ + (3 * wg + 1);
            const int qbase = 1 * TPLANE_ + 5 * TSTR_ + 5;

            u64 a0 = 0ull, a1 = 0ull, a2 = 0ull;
            #pragma unroll
            for (int dy = 0; dy < PS_; dy++) {
                const u64* crow = t8 + 2 * (cbase + dy * TSTR_) + grp;
                const u64* qrow = t8 + 2 * (qbase + dy * TSTR_) + grp;
                u64 v0 = crow[0],  v1 = crow[2],  v2 = crow[4],  v3 = crow[6];
                u64 v4 = crow[8],  v5 = crow[10], v6 = crow[12];
                u64 qv;
                qv = qrow[0];
                { u64 d; d = fma2(v0, NEG1X2_, qv); a0 = fma2(d, d, a0);
                         d = fma2(v1, NEG1X2_, qv); a1 = fma2(d, d, a1);
                         d = fma2(v2, NEG1X2_, qv); a2 = fma2(d, d, a2); }
                qv = qrow[2];
                { u64 d; d = fma2(v1, NEG1X2_, qv); a0 = fma2(d, d, a0);
                         d = fma2(v2, NEG1X2_, qv); a1 = fma2(d, d, a1);
                         d = fma2(v3, NEG1X2_, qv); a2 = fma2(d, d, a2); }
                qv = qrow[4];
                { u64 d; d = fma2(v2, NEG1X2_, qv); a0 = fma2(d, d, a0);
                         d = fma2(v3, NEG1X2_, qv); a1 = fma2(d, d, a1);
                         d = fma2(v4, NEG1X2_, qv); a2 = fma2(d, d, a2); }
                qv = qrow[6];
                { u64 d; d = fma2(v3, NEG1X2_, qv); a0 = fma2(d, d, a0);
                         d = fma2(v4, NEG1X2_, qv); a1 = fma2(d, d, a1);
                         d = fma2(v5, NEG1X2_, qv); a2 = fma2(d, d, a2); }
                qv = qrow[8];
                { u64 d; d = fma2(v4, NEG1X2_, qv); a0 = fma2(d, d, a0);
                         d = fma2(v5, NEG1X2_, qv); a1 = fma2(d, d, a1);
                         d = fma2(v6, NEG1X2_, qv); a2 = fma2(d, d, a2); }
            }
            s0 = f32x2_sum(a0);
            s1 = f32x2_sum(a1);
            s2 = f32x2_sum(a2);
            if (grp == 0) {                    // first halves stored
                dsm[cand0 + 0] = s0;
                dsm[cand0 + 1] = s1;
                dsm[cand0 + 2] = s2;
            }
        }
    } else {
        // ---- General staging (bounds-checked) ----
        for (int idx = tid; idx < 3 * TPLANE_; idx += 256) {
            int s   = idx / TPLANE_;
            int rem = idx % TPLANE_;
            int rr = rem / TSTR_, cc = rem % TSTR_;
            if (rr < Rn && cc < Cn) {
                int ft = clampi(qt + s - WT_, 0, T_ - 1);
                const float* base = nb + (size_t)ft * C_ * HW_ + (rlo + rr) * W_ + (clo + cc);
                tile4[idx] =
                    make_float4(__ldg(base), __ldg(base + HW_), __ldg(base + 2 * HW_), 0.0f);
            }
        }
        for (int idx = tid; idx < TPLANE_; idx += 256) {
            int rr = idx / TSTR_, cc = idx % TSTR_;
            if (rr < Rn && cc < Cn) {
                const float* dbase = db + (size_t)qt * C_ * HW_ + (rlo + rr) * W_ + (clo + cc);
                dtile4[idx] =
                    make_float4(__ldg(dbase), __ldg(dbase + HW_), __ldg(dbase + 2 * HW_), 0.0f);
            }
        }
        __syncthreads();

        // ---- Phase 1 general (reflect/clamp), LDS.128 per tap ----
        if (tid < L_) {
            int dti = tid / (WS_ * WS_);
            int rem = tid % (WS_ * WS_);
            int dhi = rem / WS_;
            int dwi = rem % WS_;
            int ch = clampi(qh + dhi - WS_ / 2, 0, H_ - 1);
            int cw = clampi(qw + dwi - WS_ / 2, 0, W_ - 1);
            int crow[PS_], ccol[PS_], qrow[PS_], qcol[PS_];
            #pragma unroll
            for (int d = 0; d < PS_; d++) {
                crow[d] = refl(ch + d - PS_ / 2, H_) - rlo;
                ccol[d] = refl(cw + d - PS_ / 2, W_) - clo;
                qrow[d] = refl(qh + d - PS_ / 2, H_) - rlo;
                qcol[d] = refl(qw + d - PS_ / 2, W_) - clo;
            }
            const ulonglong2* t4 = reinterpret_cast<const ulonglong2*>(tile4);
            u64 acc01 = 0ull, acc2p = 0ull;
            #pragma unroll
            for (int dy = 0; dy < PS_; dy++) {
                #pragma unroll
                for (int dx = 0; dx < PS_; dx++) {
                    int qp = 1 * TPLANE_ + qrow[dy] * TSTR_ + qcol[dx];
                    int cp = dti * TPLANE_ + crow[dy] * TSTR_ + ccol[dx];
                    ulonglong2 qv = t4[qp];
                    ulonglong2 cv = t4[cp];
                    u64 d01 = fma2(cv.x, NEG1X2_, qv.x);
                    acc01 = fma2(d01, d01, acc01);
                    u64 d2p = fma2(cv.y, NEG1X2_, qv.y);
                    acc2p = fma2(d2p, d2p, acc2p);
                }
            }
            float acc = f32x2_sum(acc01) + f32x2_sum(acc2p);
            dsm[tid] = (tid == LSELF_) ? -1.0f : acc;
        }
    }
    __syncthreads();

    // Interior: combine the two channel-halves, then mark self.
    if (interior) {
        if (tid >= 81 && tid < 162) {
            dsm[cand0 + 0] += s0;
            dsm[cand0 + 1] += s1;
            dsm[cand0 + 2] += s2;
        }
        __syncthreads();
        if (tid == 0) dsm[LSELF_] = -1.0f;
        __syncthreads();
    }

    // ---- Phase 2: K smallest via smem rescan, lowest-index tie-break (warp 0) ----
    if (tid < 32) {
        for (int k = 0; k < K_; k++) {
            float bd = FLT_MAX;
            int   bi = 1 << 20;
            for (int i = tid; i < L_; i += 32) {
                float v = dsm[i];
                if (v < bd) { bd = v; bi = i; }
            }
            #pragma unroll
            for (int off = 16; off; off >>= 1) {
                float od = __shfl_down_sync(0xffffffffu, bd, off);
                int   oi = __shfl_down_sync(0xffffffffu, bi, off);
                if (od < bd || (od == bd && oi < bi)) { bd = od; bi = oi; }
            }
            bi = __shfl_sync(0xffffffffu, bi, 0);
            if (tid == 0) { sel[k] = bi; dsm[bi] = FLT_MAX; }
            __syncwarp();
        }
    }
    __syncthreads();

    float part = 0.0f;
    const float* tf = (const float*)tile4;
    const float* df4 = (const float*)dtile4;
    if (interior) {
        if (tid < K_ - 1) {
            int l = sel[tid + 1];
            int dti = l / (WS_ * WS_);
            int rem = l % (WS_ * WS_);
            kbarr[tid] = dti * TPLANE_ + (rem / WS_) * TSTR_ + (rem % WS_);  // pixel units
        }
        __syncthreads();

        // ---- Phase 3 fast: thread = (c,dy0,dx0), pd loaded once ----
        if (tid < C_ * PSD_ * PSD_) {       // 147 threads
            int c   = tid / (PSD_ * PSD_);
            int rr  = tid % (PSD_ * PSD_);
            int dy0 = rr / PSD_;
            int dx0 = rr % PSD_;
            int mypix = dy0 * TSTR_ + dx0;
            float pd = df4[4 * ((dy0 + 4) * TSTR_ + (dx0 + 4)) + c];
            #pragma unroll
            for (int k = 0; k < K_ - 1; k++) {
                float pk = tf[4 * (kbarr[k] + mypix) + c];
                float dfv = pd - pk;
                part = fmaf(dfv, dfv, part);
            }
        }
    } else {
        if (tid < K_ - 1) {
            int l = sel[tid + 1];
            int dti = l / (WS_ * WS_);
            int rem = l % (WS_ * WS_);
            selt[tid] = dti;
            selh[tid] = clampi(qh + rem / WS_ - WS_ / 2, 0, H_ - 1);
            selw[tid] = clampi(qw + rem % WS_ - WS_ / 2, 0, W_ - 1);
        }
        __syncthreads();

        for (int i = tid; i < (K_ - 1) * C_ * PSD_ * PSD_; i += 256) {
            int k = i / (C_ * PSD_ * PSD_);
            int j = i % (C_ * PSD_ * PSD_);
            int c  = j / (PSD_ * PSD_);
            int rr = j % (PSD_ * PSD_);
            int dy = rr / PSD_ - PSD_ / 2;
            int dx = rr % PSD_ - PSD_ / 2;
            int pdp = (refl(qh + dy, H_) - rlo) * TSTR_ + (refl(qw + dx, W_) - clo);
            int pkp = selt[k] * TPLANE_ +
                      (refl(selh[k] + dy, H_) - rlo) * TSTR_ +
                      (refl(selw[k] + dx, W_) - clo);
            float pd = df4[4 * pdp + c];
            float pk = tf[4 * pkp + c];
            float dfv = pd - pk;
            part = fmaf(dfv, dfv, part);
        }
    }

    // ---- Block reduction -> atomic accumulate ----
    #pragma unroll
    for (int off = 16; off; off >>= 1)
        part += __shfl_down_sync(0xffffffffu, part, off);
    if ((tid & 31) == 0) red[tid >> 5] = part;
    __syncthreads();
    if (tid == 0) {
        float s = 0.0f;
        #pragma unroll
        for (int w = 0; w < 8; w++) s += red[w];
        atomicAdd(out, s * (1.0f / (float)(GRID_ * (K_ - 1))));
    }
}

extern "C" void kernel_launch(void* const* d_in, const int* in_sizes, int n_in,
                              void* d_out, int out_size) {
    const float* noisy = (const float*)d_in[0];
    const float* deno  = (const float*)d_in[1];
    // d_in[2] = curr_epoch (unused by the reference computation)
    zero_out_k<<<1, 1>>>((float*)d_out);
    dnls_main_k<<<GRID_, 256>>>(noisy, deno, (float*)d_out);
}